// round 2
// baseline (speedup 1.0000x reference)
#include <cuda_runtime.h>
#include <math.h>

// Shapes (fixed):
//   x:[256,128,512], W_ih:[4096,512], W_hh:[4096,1024], b_ih/b_hh:[4096]
//   W1:[1024,1024], b1:[1024], W2:[128,1024], b2:[128]
//   d_out = (output[256,128], pre_output[256,1024])
#define NB   256
#define TT   128
#define DIN  512
#define HD   1024
#define ODIM 128
#define G4   4096   // 4*HD

// -------- scratch (__device__ globals; no allocation allowed) --------
__device__ float g_xg[(size_t)NB * TT * G4];  // 512 MB, gate-interleaved cols
__device__ float g_hbuf[2][NB * HD];          // double-buffered hidden state
__device__ float g_c[NB * HD];                // cell state

__device__ __forceinline__ float sigm(float x) { return 1.0f / (1.0f + expf(-x)); }

// Logical interleaved gate column -> physical weight row.
// interleaved col n = j*4 + g  maps to  phys = g*HD + j
__device__ __forceinline__ int gate_remap(int n) {
    return (n & 3) * HD + (n >> 2);
}

// ---------------------------------------------------------------------
// C[M,N] = A[M,K] @ B[N,K]^T  (row-major / K-major operands)
// REMAP: B rows (and MODE-0 bias) indexed through gate_remap (N must be 4096)
// MODE 0: C = acc + e0[remap(n)] + e1[remap(n)]          (x-gates, interleaved out)
// MODE 2: C = relu(acc + e0[n])                          (head layer 1)
// MODE 3: C = acc + e0[n]                                (head layer 2)
// MODE 4: fused LSTM cell: gates = acc + e0[m*estride+n] (interleaved);
//         update g_c, write h to C.  Requires TN % 4 == 0.
// ---------------------------------------------------------------------
template <int BM, int BN, int BK, int TM, int TN, int MODE, bool REMAP>
__global__ __launch_bounds__((BM / TM) * (BN / TN))
void gemm_tn(const float* __restrict__ A, const float* __restrict__ B,
             float* __restrict__ C, int M, int N, int K,
             const float* __restrict__ e0, const float* __restrict__ e1,
             long estride)
{
    constexpr int THREADS = (BM / TM) * (BN / TN);
    static_assert(THREADS == 256, "tiling assumes 256 threads");
    constexpr int KV = BK / 4;                 // float4 chunks along K
    constexpr int ROWS_PER_IT = THREADS / KV;

    __shared__ float As[BK][BM + 4];
    __shared__ float Bs[BK][BN + 4];

    const int tid = threadIdx.x;
    const int tx  = tid % (BN / TN);
    const int ty  = tid / (BN / TN);
    const int rowBase = blockIdx.y * BM;
    const int colBase = blockIdx.x * BN;

    const int l_r = tid / KV;          // tile row this thread loads
    const int l_c = (tid % KV) * 4;    // k offset (float4)

    float acc[TM][TN];
#pragma unroll
    for (int i = 0; i < TM; i++)
#pragma unroll
        for (int j = 0; j < TN; j++) acc[i][j] = 0.0f;

    for (int k0 = 0; k0 < K; k0 += BK) {
#pragma unroll
        for (int r = l_r; r < BM; r += ROWS_PER_IT) {
            float4 v = *reinterpret_cast<const float4*>(
                &A[(size_t)(rowBase + r) * K + k0 + l_c]);
            As[l_c + 0][r] = v.x;
            As[l_c + 1][r] = v.y;
            As[l_c + 2][r] = v.z;
            As[l_c + 3][r] = v.w;
        }
#pragma unroll
        for (int r = l_r; r < BN; r += ROWS_PER_IT) {
            int brow = colBase + r;
            if (REMAP) brow = gate_remap(brow);
            float4 v = *reinterpret_cast<const float4*>(
                &B[(size_t)brow * K + k0 + l_c]);
            Bs[l_c + 0][r] = v.x;
            Bs[l_c + 1][r] = v.y;
            Bs[l_c + 2][r] = v.z;
            Bs[l_c + 3][r] = v.w;
        }
        __syncthreads();

#pragma unroll
        for (int kk = 0; kk < BK; kk++) {
            float ra[TM], rb[TN];
#pragma unroll
            for (int i = 0; i < TM; i++) ra[i] = As[kk][ty * TM + i];
#pragma unroll
            for (int j = 0; j < TN; j++) rb[j] = Bs[kk][tx * TN + j];
#pragma unroll
            for (int i = 0; i < TM; i++)
#pragma unroll
                for (int j = 0; j < TN; j++) acc[i][j] += ra[i] * rb[j];
        }
        __syncthreads();
    }

    // ---- epilogue ----
    if (MODE == 4) {
        // fused LSTM cell: each thread owns complete (i,f,g,o) quads
#pragma unroll
        for (int i = 0; i < TM; i++) {
            const int m = rowBase + ty * TM + i;
#pragma unroll
            for (int jj = 0; jj < TN / 4; jj++) {
                const int n0 = colBase + tx * TN + jj * 4;
                const size_t xb = (size_t)m * estride + n0;
                float v0 = acc[i][jj * 4 + 0] + e0[xb + 0];
                float v1 = acc[i][jj * 4 + 1] + e0[xb + 1];
                float v2 = acc[i][jj * 4 + 2] + e0[xb + 2];
                float v3 = acc[i][jj * 4 + 3] + e0[xb + 3];
                float ig = sigm(v0);
                float fg = sigm(v1);
                float gg = tanhf(v2);
                float og = sigm(v3);
                const size_t ci = (size_t)m * HD + (n0 >> 2);
                float c = fg * g_c[ci] + ig * gg;
                g_c[ci] = c;
                C[ci] = og * tanhf(c);   // h_out
            }
        }
    } else {
#pragma unroll
        for (int i = 0; i < TM; i++) {
            const int m = rowBase + ty * TM + i;
#pragma unroll
            for (int j = 0; j < TN; j++) {
                const int n = colBase + tx * TN + j;
                float v = acc[i][j];
                if (MODE == 0) {
                    int p = REMAP ? gate_remap(n) : n;
                    v += e0[p] + e1[p];
                } else if (MODE == 2) {
                    v += e0[n]; v = fmaxf(v, 0.0f);
                } else if (MODE == 3) {
                    v += e0[n];
                }
                C[(size_t)m * N + n] = v;
            }
        }
    }
}

// ---------------------------------------------------------------------
__global__ void zero_hc_kernel()
{
    int idx = blockIdx.x * blockDim.x + threadIdx.x;
    if (idx < NB * HD) { g_hbuf[0][idx] = 0.0f; g_c[idx] = 0.0f; }
}

// ---------------------------------------------------------------------
extern "C" void kernel_launch(void* const* d_in, const int* in_sizes, int n_in,
                              void* d_out, int out_size)
{
    const float* x    = (const float*)d_in[0];
    const float* W_ih = (const float*)d_in[1];
    const float* W_hh = (const float*)d_in[2];
    const float* b_ih = (const float*)d_in[3];
    const float* b_hh = (const float*)d_in[4];
    const float* W1   = (const float*)d_in[5];
    const float* b1   = (const float*)d_in[6];
    const float* W2   = (const float*)d_in[7];
    const float* b2   = (const float*)d_in[8];

    float* out = (float*)d_out;          // [256,128]
    float* pre = out + NB * ODIM;        // [256,1024]

    float *p_xg, *p_h0, *p_h1;
    cudaGetSymbolAddress((void**)&p_xg, g_xg);
    cudaGetSymbolAddress((void**)&p_h0, g_hbuf);
    p_h1 = p_h0 + NB * HD;

    // deterministic per-call state
    zero_hc_kernel<<<(NB * HD + 255) / 256, 256>>>();

    // 1) x_gates[NB*TT, G4] = x @ W_ih^T + b_ih + b_hh  (interleaved gate cols)
    gemm_tn<128, 128, 16, 8, 8, 0, true>
        <<<dim3(G4 / 128, (NB * TT) / 128), 256>>>(
            x, W_ih, p_xg, NB * TT, G4, DIN, b_ih, b_hh, 0);

    // 2) recurrence: 128 steps of fused (h @ W_hh^T + xg -> cell update)
    //    double-buffered h: step t reads buf[t&1], writes buf[(t+1)&1]
    for (int t = 0; t < TT; t++) {
        const float* h_in = (t & 1) ? p_h1 : p_h0;
        float* h_out      = (t & 1) ? p_h0 : p_h1;
        gemm_tn<64, 128, 16, 4, 8, 4, true>
            <<<dim3(G4 / 128, NB / 64), 256>>>(
                h_in, W_hh, h_out, NB, G4, HD,
                p_xg + (size_t)t * G4, nullptr, (long)TT * G4);
    }
    const float* h_final = p_h0;  // after 128 steps, final h in buffer 0

    // 3) pre_output = relu(h @ W1^T + b1)
    gemm_tn<64, 128, 16, 4, 8, 2, false>
        <<<dim3(HD / 128, NB / 64), 256>>>(
            h_final, W1, pre, NB, HD, HD, b1, nullptr, 0);

    // 4) output = pre_output @ W2^T + b2
    gemm_tn<64, 128, 16, 4, 8, 3, false>
        <<<dim3(ODIM / 128, NB / 64), 256>>>(
            pre, W2, out, NB, ODIM, HD, b2, nullptr, 0);
}

// round 5
// speedup vs baseline: 3.3056x; 3.3056x over previous
#include <cuda_runtime.h>
#include <cstdint>
#include <math.h>

// Shapes (fixed):
//   x:[256,128,512], W_ih:[4096,512], W_hh:[4096,1024], b_ih/b_hh:[4096]
//   W1:[1024,1024], b1:[1024], W2:[128,1024], b2:[128]
//   d_out = (output[256,128], pre_output[256,1024])
#define NB   256
#define TT   128
#define DIN  512
#define HD   1024
#define ODIM 128
#define G4   4096
#define KC   64            // K elements per pipeline chunk
#define NCHUNK 24          // (HD + DIN) / KC
#define NCH_H  16          // chunks from h @ W_hh; rest x_t @ W_ih

// -------- scratch (__device__ globals; no allocation allowed) --------
__device__ float g_h[2][NB * HD];              // double-buffered hidden state
__device__ float g_c[NB * HD];                 // cell state
__device__ float g_whh[(size_t)G4 * HD];       // RN-tf32-rounded W_hh
__device__ float g_wih[(size_t)G4 * DIN];      // RN-tf32-rounded W_ih
__device__ float g_x[(size_t)NB * TT * DIN];   // RN-tf32-rounded x

// -------- smem layout (floats) --------
#define AST 68                     // A tile row stride (pad: banks = 4g+t, conflict-free)
#define BST 68
#define AS_F (128 * AST)
#define BS_F (64 * BST)
#define OFF_AS(b) ((b) * AS_F)
#define OFF_BS(b) (2 * AS_F + (b) * BS_F)
#define OFF_BIAS  (2 * AS_F + 2 * BS_F)
#define SMEM_DYN  ((OFF_BIAS + 64) * 4)

__device__ __forceinline__ uint32_t smem_u32(const void* p) {
    uint32_t a;
    asm("{ .reg .u64 t; cvta.to.shared.u64 t, %1; cvt.u32.u64 %0, t; }"
        : "=r"(a) : "l"(p));
    return a;
}
__device__ __forceinline__ void cp16(uint32_t dst, const float* src) {
    asm volatile("cp.async.cg.shared.global [%0], [%1], 16;" :: "r"(dst), "l"(src) : "memory");
}
#define CP_COMMIT() asm volatile("cp.async.commit_group;" ::: "memory")

// m16n8k8 tf32 mma: D += A @ B  (A row-major frag, B col-major frag, f32 accum)
__device__ __forceinline__ void mma8(float* d, const uint32_t* a, const uint32_t* b) {
    asm volatile(
        "mma.sync.aligned.m16n8k8.row.col.f32.tf32.tf32.f32 "
        "{%0,%1,%2,%3}, {%4,%5,%6,%7}, {%8,%9}, {%0,%1,%2,%3};"
        : "+f"(d[0]), "+f"(d[1]), "+f"(d[2]), "+f"(d[3])
        : "r"(a[0]), "r"(a[1]), "r"(a[2]), "r"(a[3]), "r"(b[0]), "r"(b[1]));
}

__device__ __forceinline__ float sigm(float x) { return 1.0f / (1.0f + __expf(-x)); }
__device__ __forceinline__ float tanh_f(float x) {
    return fmaf(-2.0f, 1.0f / (__expf(2.0f * x) + 1.0f), 1.0f);
}

// ===================== recurrence step kernel =====================
// grid (64, 2): bx -> 16 hidden units (j0 = bx*16), by -> M-tile of 128.
// D[128,64] cols: n = warpN*32 + gate*8 + u  (unit j = j0 + warpN*8 + u).
// B tile row rr -> W row  gate(rr)*HD + j0 + (rr>>5)*8 + (rr&7), gate=(rr>>3)&3.
// K-loop: 16 chunks h@W_hh then 8 chunks x_t@W_ih, double-buffered cp.async.
__global__ __launch_bounds__(256, 1) void lstm_step_tc(
    const float* __restrict__ h_in, float* __restrict__ h_out,
    const float* __restrict__ xr, const float* __restrict__ whr,
    const float* __restrict__ wir,
    const float* __restrict__ b_ih, const float* __restrict__ b_hh, int t)
{
    extern __shared__ float sm[];
    const uint32_t sb = smem_u32(sm);
    const int tid  = threadIdx.x;
    const int wid  = tid >> 5;
    const int lane = tid & 31;
    const int j0    = blockIdx.x * 16;
    const int mBase = blockIdx.y * 128;

    if (tid < 64) {  // combined bias, indexed by tile col layout
        int phys = ((tid >> 3) & 3) * HD + j0 + (tid >> 5) * 8 + (tid & 7);
        sm[OFF_BIAS + tid] = b_ih[phys] + b_hh[phys];
    }

    auto load_chunk = [&](int c, int b) {
        const bool hc = (c < NCH_H);
        const int ka = hc ? c * KC : (c - NCH_H) * KC;
        const uint32_t ab = sb + OFF_AS(b) * 4;
        const uint32_t bbuf = sb + OFF_BS(b) * 4;
#pragma unroll
        for (int i = 0; i < 8; i++) {            // A tile: 128 x 64 f32
            int u  = tid + i * 256;
            int r  = u >> 4;
            int kl = (u & 15) * 4;
            const float* src = hc
                ? h_in + (size_t)(mBase + r) * HD + ka + kl
                : xr + ((size_t)(mBase + r) * TT + t) * DIN + ka + kl;
            cp16(ab + (r * AST + kl) * 4, src);
        }
#pragma unroll
        for (int i = 0; i < 4; i++) {            // B tile: 64 x 64 f32
            int u  = tid + i * 256;
            int rr = u >> 4;
            int kl = (u & 15) * 4;
            int phys = ((rr >> 3) & 3) * HD + j0 + (rr >> 5) * 8 + (rr & 7);
            const float* src = hc
                ? whr + (size_t)phys * HD + ka + kl
                : wir + (size_t)phys * DIN + ka + kl;
            cp16(bbuf + (rr * BST + kl) * 4, src);
        }
        CP_COMMIT();
    };

    const int warpM = wid >> 1, warpN = wid & 1;
    const int g_l = lane >> 2, t4 = lane & 3;

    float acc[2][4][4];
#pragma unroll
    for (int mi = 0; mi < 2; mi++)
#pragma unroll
        for (int ni = 0; ni < 4; ni++)
#pragma unroll
            for (int q = 0; q < 4; q++) acc[mi][ni][q] = 0.0f;

    load_chunk(0, 0);

    for (int c = 0; c < NCHUNK; c++) {
        const int b = c & 1;
        if (c + 1 < NCHUNK) {
            load_chunk(c + 1, b ^ 1);
            asm volatile("cp.async.wait_group 1;" ::: "memory");
        } else {
            asm volatile("cp.async.wait_group 0;" ::: "memory");
        }
        __syncthreads();

        const float* As = sm + OFF_AS(b);
        const float* Bs = sm + OFF_BS(b);
#pragma unroll
        for (int kk = 0; kk < 8; kk++) {
            const int k = kk * 8;
            uint32_t a[2][4], bf[4][2];
#pragma unroll
            for (int mi = 0; mi < 2; mi++) {
                const float* ar = As + (warpM * 32 + mi * 16 + g_l) * AST + k + t4;
                a[mi][0] = __float_as_uint(ar[0]);
                a[mi][1] = __float_as_uint(ar[8 * AST]);
                a[mi][2] = __float_as_uint(ar[4]);
                a[mi][3] = __float_as_uint(ar[8 * AST + 4]);
            }
#pragma unroll
            for (int ni = 0; ni < 4; ni++) {
                const float* br = Bs + (warpN * 32 + ni * 8 + g_l) * BST + k + t4;
                bf[ni][0] = __float_as_uint(br[0]);
                bf[ni][1] = __float_as_uint(br[4]);
            }
#pragma unroll
            for (int mi = 0; mi < 2; mi++)
#pragma unroll
                for (int ni = 0; ni < 4; ni++) mma8(acc[mi][ni], a[mi], bf[ni]);
        }
        __syncthreads();   // all warps done with buf b before it is reloaded
    }

    // ---- fused LSTM cell epilogue (register-resident) ----
    // thread owns units u = 2*t4 + e (e=0,1), all 4 gates, rows g_l / g_l+8 per m16.
#pragma unroll
    for (int mi = 0; mi < 2; mi++)
#pragma unroll
        for (int rr = 0; rr < 2; rr++)
#pragma unroll
            for (int e = 0; e < 2; e++) {
                const int q = rr * 2 + e;
                const int u = 2 * t4 + e;
                const int m = mBase + warpM * 32 + mi * 16 + rr * 8 + g_l;
                const int j = j0 + warpN * 8 + u;
                const float* bs = sm + OFF_BIAS + warpN * 32;
                float ig = sigm(acc[mi][0][q] + bs[0 * 8 + u]);
                float fg = sigm(acc[mi][1][q] + bs[1 * 8 + u]);
                float gg = tanh_f(acc[mi][2][q] + bs[2 * 8 + u]);
                float og = sigm(acc[mi][3][q] + bs[3 * 8 + u]);
                float* cp = g_c + (size_t)m * HD + j;
                float cv = fg * cp[0] + ig * gg;
                cp[0] = cv;
                float h = og * tanh_f(cv);
                uint32_t hb;   // RN-tf32 so next step's MMA truncation is exact
                asm("cvt.rna.tf32.f32 %0, %1;" : "=r"(hb) : "f"(h));
                h_out[(size_t)m * HD + j] = __uint_as_float(hb);
            }
}

// ===================== prep / init kernels =====================
__global__ void prep_round(const float* __restrict__ src, float* __restrict__ dst, int n) {
    int i = blockIdx.x * blockDim.x + threadIdx.x;
    if (i < n) {
        uint32_t u;
        asm("cvt.rna.tf32.f32 %0, %1;" : "=r"(u) : "f"(src[i]));
        dst[i] = __uint_as_float(u);
    }
}
__global__ void zero_hc_kernel() {
    int idx = blockIdx.x * blockDim.x + threadIdx.x;
    if (idx < NB * HD) { g_h[0][idx] = 0.0f; g_c[idx] = 0.0f; }
}

// ===================== SIMT head GEMM (exact fp32) =====================
// C[M,N] = A[M,K] @ B[N,K]^T;  MODE 2: relu(+bias), MODE 3: +bias
template <int BM, int BN, int BK, int TM, int TN, int MODE>
__global__ __launch_bounds__((BM / TM) * (BN / TN))
void gemm_tn(const float* __restrict__ A, const float* __restrict__ B,
             float* __restrict__ C, int M, int N, int K,
             const float* __restrict__ e0)
{
    constexpr int THREADS = (BM / TM) * (BN / TN);
    static_assert(THREADS == 256, "tiling assumes 256 threads");
    constexpr int KV = BK / 4;
    constexpr int ROWS_PER_IT = THREADS / KV;

    __shared__ float As[BK][BM + 4];
    __shared__ float Bs[BK][BN + 4];

    const int tid = threadIdx.x;
    const int tx  = tid % (BN / TN);
    const int ty  = tid / (BN / TN);
    const int rowBase = blockIdx.y * BM;
    const int colBase = blockIdx.x * BN;
    const int l_r = tid / KV;
    const int l_c = (tid % KV) * 4;

    float acc[TM][TN];
#pragma unroll
    for (int i = 0; i < TM; i++)
#pragma unroll
        for (int j = 0; j < TN; j++) acc[i][j] = 0.0f;

    for (int k0 = 0; k0 < K; k0 += BK) {
#pragma unroll
        for (int r = l_r; r < BM; r += ROWS_PER_IT) {
            float4 v = *reinterpret_cast<const float4*>(
                &A[(size_t)(rowBase + r) * K + k0 + l_c]);
            As[l_c + 0][r] = v.x; As[l_c + 1][r] = v.y;
            As[l_c + 2][r] = v.z; As[l_c + 3][r] = v.w;
        }
#pragma unroll
        for (int r = l_r; r < BN; r += ROWS_PER_IT) {
            float4 v = *reinterpret_cast<const float4*>(
                &B[(size_t)(colBase + r) * K + k0 + l_c]);
            Bs[l_c + 0][r] = v.x; Bs[l_c + 1][r] = v.y;
            Bs[l_c + 2][r] = v.z; Bs[l_c + 3][r] = v.w;
        }
        __syncthreads();
#pragma unroll
        for (int kk = 0; kk < BK; kk++) {
            float ra[TM], rb[TN];
#pragma unroll
            for (int i = 0; i < TM; i++) ra[i] = As[kk][ty * TM + i];
#pragma unroll
            for (int j = 0; j < TN; j++) rb[j] = Bs[kk][tx * TN + j];
#pragma unroll
            for (int i = 0; i < TM; i++)
#pragma unroll
                for (int j = 0; j < TN; j++) acc[i][j] += ra[i] * rb[j];
        }
        __syncthreads();
    }
#pragma unroll
    for (int i = 0; i < TM; i++) {
        const int m = rowBase + ty * TM + i;
#pragma unroll
        for (int j = 0; j < TN; j++) {
            const int n = colBase + tx * TN + j;
            float v = acc[i][j] + e0[n];
            if (MODE == 2) v = fmaxf(v, 0.0f);
            C[(size_t)m * N + n] = v;
        }
    }
}

// ===================== launch =====================
extern "C" void kernel_launch(void* const* d_in, const int* in_sizes, int n_in,
                              void* d_out, int out_size)
{
    const float* x    = (const float*)d_in[0];
    const float* W_ih = (const float*)d_in[1];
    const float* W_hh = (const float*)d_in[2];
    const float* b_ih = (const float*)d_in[3];
    const float* b_hh = (const float*)d_in[4];
    const float* W1   = (const float*)d_in[5];
    const float* b1   = (const float*)d_in[6];
    const float* W2   = (const float*)d_in[7];
    const float* b2   = (const float*)d_in[8];

    float* out = (float*)d_out;          // [256,128]
    float* pre = out + NB * ODIM;        // [256,1024]

    float *p_h0, *p_h1, *p_whh, *p_wih, *p_x;
    cudaGetSymbolAddress((void**)&p_h0, g_h);
    p_h1 = p_h0 + NB * HD;
    cudaGetSymbolAddress((void**)&p_whh, g_whh);
    cudaGetSymbolAddress((void**)&p_wih, g_wih);
    cudaGetSymbolAddress((void**)&p_x, g_x);

    cudaFuncSetAttribute(lstm_step_tc, cudaFuncAttributeMaxDynamicSharedMemorySize, SMEM_DYN);

    zero_hc_kernel<<<(NB * HD + 255) / 256, 256>>>();
    prep_round<<<(G4 * HD + 255) / 256, 256>>>(W_hh, p_whh, G4 * HD);
    prep_round<<<(G4 * DIN + 255) / 256, 256>>>(W_ih, p_wih, G4 * DIN);
    prep_round<<<(NB * TT * DIN + 255) / 256, 256>>>(x, p_x, NB * TT * DIN);

    // recurrence: 128 fused (h@W_hh + x_t@W_ih -> cell) tensor-core steps
    for (int t = 0; t < TT; t++) {
        const float* h_in = (t & 1) ? p_h1 : p_h0;
        float* h_out      = (t & 1) ? p_h0 : p_h1;
        lstm_step_tc<<<dim3(64, 2), 256, SMEM_DYN>>>(
            h_in, h_out, p_x, p_whh, p_wih, b_ih, b_hh, t);
    }
    const float* h_final = p_h0;  // t=127 writes buffer 0

    // head (exact fp32 SIMT)
    gemm_tn<64, 128, 16, 4, 8, 2><<<dim3(HD / 128, NB / 64), 256>>>(
        h_final, W1, pre, NB, HD, HD, b1);
    gemm_tn<64, 128, 16, 4, 8, 3><<<dim3(ODIM / 128, NB / 64), 256>>>(
        pre, W2, out, NB, ODIM, HD, b2);
}

// round 8
// speedup vs baseline: 3.3815x; 1.0230x over previous
#include <cuda_runtime.h>
#include <cstdint>
#include <math.h>

// Shapes (fixed):
//   x:[256,128,512], W_ih:[4096,512], W_hh:[4096,1024], b_ih/b_hh:[4096]
//   W1:[1024,1024], b1:[1024], W2:[128,1024], b2:[128]
//   d_out = (output[256,128], pre_output[256,1024])
#define NB   256
#define TT   128
#define DIN  512
#define HD   1024
#define ODIM 128
#define G4   4096
#define KC   96            // K elements per chunk (unified h|x K-space, 1536 total)
#define NCHUNK 16          // 1536 / 96

// -------- scratch (__device__ globals; no allocation allowed) --------
__device__ float g_h[2][NB * HD];              // ping-pong hidden state
__device__ float g_c[NB * HD];                 // cell state
__device__ float g_whh[(size_t)G4 * HD];       // RN-tf32-rounded W_hh
__device__ float g_wih[(size_t)G4 * DIN];      // RN-tf32-rounded W_ih
__device__ float g_x[(size_t)NB * TT * DIN];   // RN-tf32-rounded x

// -------- smem: 3-stage circular buffer (one sync per chunk) --------
#define AST 100                    // KC + 4 pad (100 mod 32 = 4 -> conflict-free)
#define BST 100
#define AS_F (128 * AST)
#define BS_F (64 * BST)
#define OFF_AS(s) ((s) * AS_F)
#define OFF_BS(s) (3 * AS_F + (s) * BS_F)
#define OFF_BIAS  (3 * (AS_F + BS_F))
#define SMEM_DYN  ((OFF_BIAS + 64) * 4)        // 230,656 B (< 227 KB limit)

__device__ __forceinline__ uint32_t smem_u32(const void* p) {
    uint32_t a;
    asm("{ .reg .u64 t; cvta.to.shared.u64 t, %1; cvt.u32.u64 %0, t; }"
        : "=r"(a) : "l"(p));
    return a;
}
__device__ __forceinline__ void cp16(uint32_t dst, const float* src) {
    asm volatile("cp.async.cg.shared.global [%0], [%1], 16;" :: "r"(dst), "l"(src) : "memory");
}
#define CP_COMMIT() asm volatile("cp.async.commit_group;" ::: "memory")

__device__ __forceinline__ void mma8(float* d, const uint32_t* a, const uint32_t* b) {
    asm volatile(
        "mma.sync.aligned.m16n8k8.row.col.f32.tf32.tf32.f32 "
        "{%0,%1,%2,%3}, {%4,%5,%6,%7}, {%8,%9}, {%0,%1,%2,%3};"
        : "+f"(d[0]), "+f"(d[1]), "+f"(d[2]), "+f"(d[3])
        : "r"(a[0]), "r"(a[1]), "r"(a[2]), "r"(a[3]), "r"(b[0]), "r"(b[1]));
}

__device__ __forceinline__ float sigm(float x) { return 1.0f / (1.0f + __expf(-x)); }
__device__ __forceinline__ float tanh_f(float x) {
    return fmaf(-2.0f, 1.0f / (__expf(2.0f * x) + 1.0f), 1.0f);
}

// ===================== recurrence step kernel =====================
// grid (64,2): bx -> 16 hidden units (j0), by -> M-tile of 128.
// D[128,64] cols: n = warpN*32 + gate*8 + u. B tile row rr -> W row
// gate(rr)*HD + j0 + (rr>>5)*8 + (rr&7), gate = (rr>>3)&3.
// Unified K: kg in [0,1536); kg<1024 -> h@W_hh, else x_t@W_ih.
__global__ __launch_bounds__(256, 1) void lstm_step_tc(
    const float* __restrict__ h_in, float* __restrict__ h_out,
    const float* __restrict__ xr, const float* __restrict__ whr,
    const float* __restrict__ wir,
    const float* __restrict__ b_ih, const float* __restrict__ b_hh, int t)
{
    extern __shared__ float sm[];
    const uint32_t sb = smem_u32(sm);
    const int tid  = threadIdx.x;
    const int wid  = tid >> 5;
    const int lane = tid & 31;
    const int j0    = blockIdx.x * 16;
    const int mBase = blockIdx.y * 128;
    const int warpM = wid >> 1, warpN = wid & 1;
    const int g_l = lane >> 2, t4 = lane & 3;

    if (tid < 64) {
        int phys = ((tid >> 3) & 3) * HD + j0 + (tid >> 5) * 8 + (tid & 7);
        sm[OFF_BIAS + tid] = b_ih[phys] + b_hh[phys];
    }

    auto load_chunk = [&](int c, int s) {
        const uint32_t ab   = sb + OFF_AS(s) * 4;
        const uint32_t bbuf = sb + OFF_BS(s) * 4;
#pragma unroll
        for (int i = 0; i < 12; i++) {           // A tile: 128 rows x 96 f32 (24 f4/row)
            int u  = tid + i * 256;
            int r  = u / 24;
            int kl = (u % 24) * 4;
            int kg = c * KC + kl;
            const float* src = (kg < HD)
                ? h_in + (size_t)(mBase + r) * HD + kg
                : xr + ((size_t)(mBase + r) * TT + t) * DIN + (kg - HD);
            cp16(ab + (r * AST + kl) * 4, src);
        }
#pragma unroll
        for (int i = 0; i < 6; i++) {            // B tile: 64 rows x 96 f32
            int u  = tid + i * 256;
            int rr = u / 24;
            int kl = (u % 24) * 4;
            int kg = c * KC + kl;
            int phys = ((rr >> 3) & 3) * HD + j0 + (rr >> 5) * 8 + (rr & 7);
            const float* src = (kg < HD)
                ? whr + (size_t)phys * HD + kg
                : wir + (size_t)phys * DIN + (kg - HD);
            cp16(bbuf + (rr * BST + kl) * 4, src);
        }
        CP_COMMIT();
    };

    float acc[2][4][4];
#pragma unroll
    for (int mi = 0; mi < 2; mi++)
#pragma unroll
        for (int ni = 0; ni < 4; ni++)
#pragma unroll
            for (int q = 0; q < 4; q++) acc[mi][ni][q] = 0.0f;

    // prologue: chunks 0,1 into stages 0,1
    load_chunk(0, 0);
    load_chunk(1, 1);

    for (int c = 0; c < NCHUNK; c++) {
        if (c + 1 < NCHUNK) asm volatile("cp.async.wait_group 1;" ::: "memory");
        else                asm volatile("cp.async.wait_group 0;" ::: "memory");
        __syncthreads();     // chunk c visible; all warps done with stage (c+2)%3
        if (c + 2 < NCHUNK) load_chunk(c + 2, (c + 2) % 3);

        const float* As = sm + OFF_AS(c % 3);
        const float* Bs = sm + OFF_BS(c % 3);
#pragma unroll
        for (int kk = 0; kk < 12; kk++) {
            const int k = kk * 8;
            uint32_t a[2][4], bf[4][2];
#pragma unroll
            for (int mi = 0; mi < 2; mi++) {
                const float* ar = As + (warpM * 32 + mi * 16 + g_l) * AST + k + t4;
                a[mi][0] = __float_as_uint(ar[0]);
                a[mi][1] = __float_as_uint(ar[8 * AST]);
                a[mi][2] = __float_as_uint(ar[4]);
                a[mi][3] = __float_as_uint(ar[8 * AST + 4]);
            }
#pragma unroll
            for (int ni = 0; ni < 4; ni++) {
                const float* br = Bs + (warpN * 32 + ni * 8 + g_l) * BST + k + t4;
                bf[ni][0] = __float_as_uint(br[0]);
                bf[ni][1] = __float_as_uint(br[4]);
            }
#pragma unroll
            for (int mi = 0; mi < 2; mi++)
#pragma unroll
                for (int ni = 0; ni < 4; ni++) mma8(acc[mi][ni], a[mi], bf[ni]);
        }
    }

    // ---- fused LSTM cell epilogue (register-resident accumulators) ----
#pragma unroll
    for (int mi = 0; mi < 2; mi++)
#pragma unroll
        for (int rr = 0; rr < 2; rr++)
#pragma unroll
            for (int e = 0; e < 2; e++) {
                const int q = rr * 2 + e;
                const int u = 2 * t4 + e;
                const int m = mBase + warpM * 32 + mi * 16 + rr * 8 + g_l;
                const int j = j0 + warpN * 8 + u;
                const float* bs = sm + OFF_BIAS + warpN * 32;
                float ig = sigm(acc[mi][0][q] + bs[0 * 8 + u]);
                float fg = sigm(acc[mi][1][q] + bs[1 * 8 + u]);
                float gg = tanh_f(acc[mi][2][q] + bs[2 * 8 + u]);
                float og = sigm(acc[mi][3][q] + bs[3 * 8 + u]);
                float* cp = g_c + (size_t)m * HD + j;
                float cv = fg * cp[0] + ig * gg;
                cp[0] = cv;
                float h = og * tanh_f(cv);
                uint32_t hb;   // RN-tf32: next step's MMA reads it exactly
                asm("cvt.rna.tf32.f32 %0, %1;" : "=r"(hb) : "f"(h));
                h_out[(size_t)m * HD + j] = __uint_as_float(hb);
            }
}

// ===================== prep / init kernels =====================
__global__ void prep_round4(const float4* __restrict__ src, float4* __restrict__ dst, int n4) {
    int i = blockIdx.x * blockDim.x + threadIdx.x;
    if (i < n4) {
        float4 v = src[i];
        uint32_t a, b, c, d;
        asm("cvt.rna.tf32.f32 %0, %1;" : "=r"(a) : "f"(v.x));
        asm("cvt.rna.tf32.f32 %0, %1;" : "=r"(b) : "f"(v.y));
        asm("cvt.rna.tf32.f32 %0, %1;" : "=r"(c) : "f"(v.z));
        asm("cvt.rna.tf32.f32 %0, %1;" : "=r"(d) : "f"(v.w));
        dst[i] = make_float4(__uint_as_float(a), __uint_as_float(b),
                             __uint_as_float(c), __uint_as_float(d));
    }
}
__global__ void zero_hc_kernel() {
    int idx = blockIdx.x * blockDim.x + threadIdx.x;
    if (idx < NB * HD) { g_h[0][idx] = 0.0f; g_c[idx] = 0.0f; }
}

// ===================== SIMT head GEMM (exact fp32) =====================
template <int BM, int BN, int BK, int TM, int TN, int MODE>
__global__ __launch_bounds__((BM / TM) * (BN / TN))
void gemm_tn(const float* __restrict__ A, const float* __restrict__ B,
             float* __restrict__ C, int M, int N, int K,
             const float* __restrict__ e0)
{
    constexpr int THREADS = (BM / TM) * (BN / TN);
    static_assert(THREADS == 256, "tiling assumes 256 threads");
    constexpr int KV = BK / 4;
    constexpr int ROWS_PER_IT = THREADS / KV;

    __shared__ float As[BK][BM + 4];
    __shared__ float Bs[BK][BN + 4];

    const int tid = threadIdx.x;
    const int tx  = tid % (BN / TN);
    const int ty  = tid / (BN / TN);
    const int rowBase = blockIdx.y * BM;
    const int colBase = blockIdx.x * BN;
    const int l_r = tid / KV;
    const int l_c = (tid % KV) * 4;

    float acc[TM][TN];
#pragma unroll
    for (int i = 0; i < TM; i++)
#pragma unroll
        for (int j = 0; j < TN; j++) acc[i][j] = 0.0f;

    for (int k0 = 0; k0 < K; k0 += BK) {
#pragma unroll
        for (int r = l_r; r < BM; r += ROWS_PER_IT) {
            float4 v = *reinterpret_cast<const float4*>(
                &A[(size_t)(rowBase + r) * K + k0 + l_c]);
            As[l_c + 0][r] = v.x; As[l_c + 1][r] = v.y;
            As[l_c + 2][r] = v.z; As[l_c + 3][r] = v.w;
        }
#pragma unroll
        for (int r = l_r; r < BN; r += ROWS_PER_IT) {
            float4 v = *reinterpret_cast<const float4*>(
                &B[(size_t)(colBase + r) * K + k0 + l_c]);
            Bs[l_c + 0][r] = v.x; Bs[l_c + 1][r] = v.y;
            Bs[l_c + 2][r] = v.z; Bs[l_c + 3][r] = v.w;
        }
        __syncthreads();
#pragma unroll
        for (int kk = 0; kk < BK; kk++) {
            float ra[TM], rb[TN];
#pragma unroll
            for (int i = 0; i < TM; i++) ra[i] = As[kk][ty * TM + i];
#pragma unroll
            for (int j = 0; j < TN; j++) rb[j] = Bs[kk][tx * TN + j];
#pragma unroll
            for (int i = 0; i < TM; i++)
#pragma unroll
                for (int j = 0; j < TN; j++) acc[i][j] += ra[i] * rb[j];
        }
        __syncthreads();
    }
#pragma unroll
    for (int i = 0; i < TM; i++) {
        const int m = rowBase + ty * TM + i;
#pragma unroll
        for (int j = 0; j < TN; j++) {
            const int n = colBase + tx * TN + j;
            float v = acc[i][j] + e0[n];
            if (MODE == 2) v = fmaxf(v, 0.0f);
            C[(size_t)m * N + n] = v;
        }
    }
}

// ===================== launch =====================
extern "C" void kernel_launch(void* const* d_in, const int* in_sizes, int n_in,
                              void* d_out, int out_size)
{
    const float* x    = (const float*)d_in[0];
    const float* W_ih = (const float*)d_in[1];
    const float* W_hh = (const float*)d_in[2];
    const float* b_ih = (const float*)d_in[3];
    const float* b_hh = (const float*)d_in[4];
    const float* W1   = (const float*)d_in[5];
    const float* b1   = (const float*)d_in[6];
    const float* W2   = (const float*)d_in[7];
    const float* b2   = (const float*)d_in[8];

    float* out = (float*)d_out;          // [256,128]
    float* pre = out + NB * ODIM;        // [256,1024]

    float *p_h0, *p_h1, *p_whh, *p_wih, *p_x;
    cudaGetSymbolAddress((void**)&p_h0, g_h);
    p_h1 = p_h0 + NB * HD;
    cudaGetSymbolAddress((void**)&p_whh, g_whh);
    cudaGetSymbolAddress((void**)&p_wih, g_wih);
    cudaGetSymbolAddress((void**)&p_x, g_x);

    cudaFuncSetAttribute(lstm_step_tc, cudaFuncAttributeMaxDynamicSharedMemorySize, SMEM_DYN);

    zero_hc_kernel<<<(NB * HD + 255) / 256, 256>>>();
    prep_round4<<<(G4 * HD / 4 + 255) / 256, 256>>>((const float4*)W_hh, (float4*)p_whh, G4 * HD / 4);
    prep_round4<<<(G4 * DIN / 4 + 255) / 256, 256>>>((const float4*)W_ih, (float4*)p_wih, G4 * DIN / 4);
    prep_round4<<<(NB * TT * DIN / 4 + 255) / 256, 256>>>((const float4*)x, (float4*)p_x, NB * TT * DIN / 4);

    // recurrence: 128 fused (h@W_hh + x_t@W_ih -> cell) tensor-core steps
    for (int t = 0; t < TT; t++) {
        const float* h_in = (t & 1) ? p_h1 : p_h0;
        float* h_out      = (t & 1) ? p_h0 : p_h1;
        lstm_step_tc<<<dim3(64, 2), 256, SMEM_DYN>>>(
            h_in, h_out, p_x, p_whh, p_wih, b_ih, b_hh, t);
    }
    const float* h_final = p_h0;  // t=127 writes buffer 0

    // head (exact fp32 SIMT)
    gemm_tn<64, 128, 16, 4, 8, 2><<<dim3(HD / 128, NB / 64), 256>>>(
        h_final, W1, pre, NB, HD, HD, b1);
    gemm_tn<64, 128, 16, 4, 8, 3><<<dim3(ODIM / 128, NB / 64), 256>>>(
        pre, W2, out, NB, ODIM, HD, b2);
}

// round 10
// speedup vs baseline: 5.3905x; 1.5941x over previous
#include <cuda_runtime.h>
#include <cuda_fp16.h>
#include <cstdint>
#include <math.h>

// Shapes (fixed):
//   x:[256,128,512], W_ih:[4096,512], W_hh:[4096,1024], b_ih/b_hh:[4096]
//   W1:[1024,1024], b1:[1024], W2:[128,1024], b2:[128]
//   d_out = (output[256,128], pre_output[256,1024])
#define NB   256
#define TT   128
#define DIN  512
#define HD   1024
#define ODIM 128
#define G4   4096
#define KC   128           // K halves per chunk (unified h|x K-space, 1536 total)
#define NCHUNK 12          // 1536 / 128

// -------- scratch (__device__ globals; no allocation allowed) --------
__device__ __half g_h[2][NB * HD];             // ping-pong hidden state (fp16)
__device__ float  g_hf[NB * HD];               // final h in fp32 for head
__device__ float  g_c[NB * HD];                // cell state (fp32)
__device__ __half g_whh[(size_t)G4 * HD];      // RN-fp16 W_hh
__device__ __half g_wih[(size_t)G4 * DIN];     // RN-fp16 W_ih
__device__ __half g_x[(size_t)NB * TT * DIN];  // RN-fp16 x

// -------- smem: 3-stage circular buffer, fp16 tiles --------
// Row stride 136 halves = 68 words; word index = row*68 + t4 -> bank
// (4*row + t4) mod 32: conflict-free for all fragment loads.
#define ASTW 68                                 // row stride in 32-bit words
#define A_BYTES (128 * ASTW * 4)                // 34,816 B per stage
#define B_BYTES (64 * ASTW * 4)                 // 17,408 B per stage
#define OFF_AS(s) ((s) * A_BYTES)
#define OFF_BS(s) (3 * A_BYTES + (s) * B_BYTES)
#define OFF_BIAS  (3 * (A_BYTES + B_BYTES))
#define SMEM_DYN  (OFF_BIAS + 256)              // 156,928 B (< 227 KB)

__device__ __forceinline__ uint32_t smem_u32(const void* p) {
    uint32_t a;
    asm("{ .reg .u64 t; cvta.to.shared.u64 t, %1; cvt.u32.u64 %0, t; }"
        : "=r"(a) : "l"(p));
    return a;
}
__device__ __forceinline__ void cp16(uint32_t dst, const void* src) {
    asm volatile("cp.async.cg.shared.global [%0], [%1], 16;" :: "r"(dst), "l"(src) : "memory");
}
#define CP_COMMIT() asm volatile("cp.async.commit_group;" ::: "memory")

// fp16 m16n8k16, fp32 accumulate: D += A(row) @ B(col)
__device__ __forceinline__ void mma16(float* d, const uint32_t* a, const uint32_t* b) {
    asm volatile(
        "mma.sync.aligned.m16n8k16.row.col.f32.f16.f16.f32 "
        "{%0,%1,%2,%3}, {%4,%5,%6,%7}, {%8,%9}, {%0,%1,%2,%3};"
        : "+f"(d[0]), "+f"(d[1]), "+f"(d[2]), "+f"(d[3])
        : "r"(a[0]), "r"(a[1]), "r"(a[2]), "r"(a[3]), "r"(b[0]), "r"(b[1]));
}

__device__ __forceinline__ float sigm(float x) { return 1.0f / (1.0f + __expf(-x)); }
__device__ __forceinline__ float tanh_f(float x) {
    return fmaf(-2.0f, 1.0f / (__expf(2.0f * x) + 1.0f), 1.0f);
}

// ===================== recurrence step kernel =====================
// grid (64,2): bx -> 16 hidden units (j0), by -> M-tile of 128.
// D[128,64] cols: n = warpN*32 + gate*8 + u. B tile row rr -> W row
// gate(rr)*HD + j0 + (rr>>5)*8 + (rr&7), gate = (rr>>3)&3.
// Unified K: kg in [0,1536); kg<1024 -> h@W_hh, else x_t@W_ih.
__global__ __launch_bounds__(256, 1) void lstm_step_tc(
    const __half* __restrict__ h_in, __half* __restrict__ h_out,
    const __half* __restrict__ xr, const __half* __restrict__ whr,
    const __half* __restrict__ wir,
    const float* __restrict__ b_ih, const float* __restrict__ b_hh, int t)
{
    extern __shared__ char smc[];
    const uint32_t sb = smem_u32(smc);
    float* biasS = (float*)(smc + OFF_BIAS);
    const int tid  = threadIdx.x;
    const int wid  = tid >> 5;
    const int lane = tid & 31;
    const int j0    = blockIdx.x * 16;
    const int mBase = blockIdx.y * 128;
    const int warpM = wid >> 1, warpN = wid & 1;
    const int g_l = lane >> 2, t4 = lane & 3;

    if (tid < 64) {
        int phys = ((tid >> 3) & 3) * HD + j0 + (tid >> 5) * 8 + (tid & 7);
        biasS[tid] = b_ih[phys] + b_hh[phys];
    }

    auto load_chunk = [&](int c, int s) {
        const uint32_t ab   = sb + OFF_AS(s);
        const uint32_t bbuf = sb + OFF_BS(s);
#pragma unroll
        for (int i = 0; i < 8; i++) {            // A tile: 128 rows x 128 halves
            int u   = tid + i * 256;             // 16 units (8 halves) per row
            int r   = u >> 4;
            int kl8 = (u & 15) * 8;
            int kg  = c * KC + kl8;
            const __half* src = (kg < HD)
                ? h_in + (size_t)(mBase + r) * HD + kg
                : xr + ((size_t)(mBase + r) * TT + t) * DIN + (kg - HD);
            cp16(ab + (r * ASTW * 4 + kl8 * 2), src);
        }
#pragma unroll
        for (int i = 0; i < 4; i++) {            // B tile: 64 rows x 128 halves
            int u   = tid + i * 256;
            int rr  = u >> 4;
            int kl8 = (u & 15) * 8;
            int kg  = c * KC + kl8;
            int phys = ((rr >> 3) & 3) * HD + j0 + (rr >> 5) * 8 + (rr & 7);
            const __half* src = (kg < HD)
                ? whr + (size_t)phys * HD + kg
                : wir + (size_t)phys * DIN + (kg - HD);
            cp16(bbuf + (rr * ASTW * 4 + kl8 * 2), src);
        }
        CP_COMMIT();
    };

    float acc[2][4][4];
#pragma unroll
    for (int mi = 0; mi < 2; mi++)
#pragma unroll
        for (int ni = 0; ni < 4; ni++)
#pragma unroll
            for (int q = 0; q < 4; q++) acc[mi][ni][q] = 0.0f;

    load_chunk(0, 0);
    load_chunk(1, 1);

    for (int c = 0; c < NCHUNK; c++) {
        if (c + 1 < NCHUNK) asm volatile("cp.async.wait_group 1;" ::: "memory");
        else                asm volatile("cp.async.wait_group 0;" ::: "memory");
        __syncthreads();     // chunk c visible; all warps done with stage (c+2)%3
        if (c + 2 < NCHUNK) load_chunk(c + 2, (c + 2) % 3);

        const uint32_t* As = (const uint32_t*)(smc + OFF_AS(c % 3));
        const uint32_t* Bs = (const uint32_t*)(smc + OFF_BS(c % 3));
#pragma unroll
        for (int kk = 0; kk < 8; kk++) {         // 8 x k16 per chunk
            const int kw = kk * 8;               // word offset (16 halves)
            uint32_t a[2][4], bf[4][2];
#pragma unroll
            for (int mi = 0; mi < 2; mi++) {
                const uint32_t* ar = As + (warpM * 32 + mi * 16 + g_l) * ASTW + kw + t4;
                a[mi][0] = ar[0];                // row g_l,   k 2t4..2t4+1
                a[mi][1] = ar[8 * ASTW];         // row g_l+8
                a[mi][2] = ar[4];                // k +8
                a[mi][3] = ar[8 * ASTW + 4];
            }
#pragma unroll
            for (int ni = 0; ni < 4; ni++) {
                const uint32_t* br = Bs + (warpN * 32 + ni * 8 + g_l) * ASTW + kw + t4;
                bf[ni][0] = br[0];               // n g_l, k 2t4..2t4+1
                bf[ni][1] = br[4];               // k +8
            }
#pragma unroll
            for (int mi = 0; mi < 2; mi++)
#pragma unroll
                for (int ni = 0; ni < 4; ni++) mma16(acc[mi][ni], a[mi], bf[ni]);
        }
    }

    // ---- fused LSTM cell epilogue ----
#pragma unroll
    for (int mi = 0; mi < 2; mi++)
#pragma unroll
        for (int rr = 0; rr < 2; rr++)
#pragma unroll
            for (int e = 0; e < 2; e++) {
                const int q = rr * 2 + e;
                const int u = 2 * t4 + e;
                const int m = mBase + warpM * 32 + mi * 16 + rr * 8 + g_l;
                const int j = j0 + warpN * 8 + u;
                const float* bs = biasS + warpN * 32;
                float ig = sigm(acc[mi][0][q] + bs[0 * 8 + u]);
                float fg = sigm(acc[mi][1][q] + bs[1 * 8 + u]);
                float gg = tanh_f(acc[mi][2][q] + bs[2 * 8 + u]);
                float og = sigm(acc[mi][3][q] + bs[3 * 8 + u]);
                float* cp = g_c + (size_t)m * HD + j;
                float cv = fg * cp[0] + ig * gg;
                cp[0] = cv;
                float h = og * tanh_f(cv);
                h_out[(size_t)m * HD + j] = __float2half_rn(h);
            }
}

// ===================== prep / init kernels =====================
__global__ void prep_half(const float4* __restrict__ src, __half2* __restrict__ dst, int n4) {
    int i = blockIdx.x * blockDim.x + threadIdx.x;
    if (i < n4) {
        float4 v = src[i];
        dst[2 * i + 0] = __floats2half2_rn(v.x, v.y);
        dst[2 * i + 1] = __floats2half2_rn(v.z, v.w);
    }
}
__global__ void zero_hc_kernel() {
    int idx = blockIdx.x * blockDim.x + threadIdx.x;
    if (idx < NB * HD) { g_h[0][idx] = __float2half(0.0f); g_c[idx] = 0.0f; }
}
__global__ void h2f_kernel(const __half* __restrict__ h, float* __restrict__ f, int n) {
    int i = blockIdx.x * blockDim.x + threadIdx.x;
    if (i < n) f[i] = __half2float(h[i]);
}

// ===================== SIMT head GEMM (exact fp32) =====================
template <int BM, int BN, int BK, int TM, int TN, int MODE>
__global__ __launch_bounds__((BM / TM) * (BN / TN))
void gemm_tn(const float* __restrict__ A, const float* __restrict__ B,
             float* __restrict__ C, int M, int N, int K,
             const float* __restrict__ e0)
{
    constexpr int THREADS = (BM / TM) * (BN / TN);
    static_assert(THREADS == 256, "tiling assumes 256 threads");
    constexpr int KV = BK / 4;
    constexpr int ROWS_PER_IT = THREADS / KV;

    __shared__ float As[BK][BM + 4];
    __shared__ float Bs[BK][BN + 4];

    const int tid = threadIdx.x;
    const int tx  = tid % (BN / TN);
    const int ty  = tid / (BN / TN);
    const int rowBase = blockIdx.y * BM;
    const int colBase = blockIdx.x * BN;
    const int l_r = tid / KV;
    const int l_c = (tid % KV) * 4;

    float acc[TM][TN];
#pragma unroll
    for (int i = 0; i < TM; i++)
#pragma unroll
        for (int j = 0; j < TN; j++) acc[i][j] = 0.0f;

    for (int k0 = 0; k0 < K; k0 += BK) {
#pragma unroll
        for (int r = l_r; r < BM; r += ROWS_PER_IT) {
            float4 v = *reinterpret_cast<const float4*>(
                &A[(size_t)(rowBase + r) * K + k0 + l_c]);
            As[l_c + 0][r] = v.x; As[l_c + 1][r] = v.y;
            As[l_c + 2][r] = v.z; As[l_c + 3][r] = v.w;
        }
#pragma unroll
        for (int r = l_r; r < BN; r += ROWS_PER_IT) {
            float4 v = *reinterpret_cast<const float4*>(
                &B[(size_t)(colBase + r) * K + k0 + l_c]);
            Bs[l_c + 0][r] = v.x; Bs[l_c + 1][r] = v.y;
            Bs[l_c + 2][r] = v.z; Bs[l_c + 3][r] = v.w;
        }
        __syncthreads();
#pragma unroll
        for (int kk = 0; kk < BK; kk++) {
            float ra[TM], rb[TN];
#pragma unroll
            for (int i = 0; i < TM; i++) ra[i] = As[kk][ty * TM + i];
#pragma unroll
            for (int j = 0; j < TN; j++) rb[j] = Bs[kk][tx * TN + j];
#pragma unroll
            for (int i = 0; i < TM; i++)
#pragma unroll
                for (int j = 0; j < TN; j++) acc[i][j] += ra[i] * rb[j];
        }
        __syncthreads();
    }
#pragma unroll
    for (int i = 0; i < TM; i++) {
        const int m = rowBase + ty * TM + i;
#pragma unroll
        for (int j = 0; j < TN; j++) {
            const int n = colBase + tx * TN + j;
            float v = acc[i][j] + e0[n];
            if (MODE == 2) v = fmaxf(v, 0.0f);
            C[(size_t)m * N + n] = v;
        }
    }
}

// ===================== launch =====================
extern "C" void kernel_launch(void* const* d_in, const int* in_sizes, int n_in,
                              void* d_out, int out_size)
{
    const float* x    = (const float*)d_in[0];
    const float* W_ih = (const float*)d_in[1];
    const float* W_hh = (const float*)d_in[2];
    const float* b_ih = (const float*)d_in[3];
    const float* b_hh = (const float*)d_in[4];
    const float* W1   = (const float*)d_in[5];
    const float* b1   = (const float*)d_in[6];
    const float* W2   = (const float*)d_in[7];
    const float* b2   = (const float*)d_in[8];

    float* out = (float*)d_out;          // [256,128]
    float* pre = out + NB * ODIM;        // [256,1024]

    __half *p_h0, *p_h1, *p_whh, *p_wih, *p_x;
    float *p_hf;
    cudaGetSymbolAddress((void**)&p_h0, g_h);
    p_h1 = p_h0 + NB * HD;
    cudaGetSymbolAddress((void**)&p_hf, g_hf);
    cudaGetSymbolAddress((void**)&p_whh, g_whh);
    cudaGetSymbolAddress((void**)&p_wih, g_wih);
    cudaGetSymbolAddress((void**)&p_x, g_x);

    cudaFuncSetAttribute(lstm_step_tc, cudaFuncAttributeMaxDynamicSharedMemorySize, SMEM_DYN);

    zero_hc_kernel<<<(NB * HD + 255) / 256, 256>>>();
    prep_half<<<(G4 * HD / 4 + 255) / 256, 256>>>((const float4*)W_hh, (__half2*)p_whh, G4 * HD / 4);
    prep_half<<<(G4 * DIN / 4 + 255) / 256, 256>>>((const float4*)W_ih, (__half2*)p_wih, G4 * DIN / 4);
    prep_half<<<(NB * TT * DIN / 4 + 255) / 256, 256>>>((const float4*)x, (__half2*)p_x, NB * TT * DIN / 4);

    // recurrence: 128 fused (h@W_hh + x_t@W_ih -> cell) fp16 tensor-core steps
    for (int t = 0; t < TT; t++) {
        const __half* h_in = (t & 1) ? p_h1 : p_h0;
        __half* h_out      = (t & 1) ? p_h0 : p_h1;
        lstm_step_tc<<<dim3(64, 2), 256, SMEM_DYN>>>(
            h_in, h_out, p_x, p_whh, p_wih, b_ih, b_hh, t);
    }

    // final h (buffer 0 after even step count) -> fp32 for exact head GEMMs
    h2f_kernel<<<(NB * HD + 255) / 256, 256>>>(p_h0, p_hf, NB * HD);

    gemm_tn<64, 128, 16, 4, 8, 2><<<dim3(HD / 128, NB / 64), 256>>>(
        p_hf, W1, pre, NB, HD, HD, b1);
    gemm_tn<64, 128, 16, 4, 8, 3><<<dim3(ODIM / 128, NB / 64), 256>>>(
        pre, W2, out, NB, ODIM, HD, b2);
}